// round 13
// baseline (speedup 1.0000x reference)
#include <cuda_runtime.h>
#include <cuda_bf16.h>
#include <math.h>
#include <stdint.h>

#define B 128
#define T_STEPS 200
#define NH 2048
#define NI 32
#define PORT 1024
#define DT 0.042f
#define THRESH 0.5f

#define SPLITK 4
#define KSLICE 512            // K per CTA
#define KC 64                 // K per A smem stage (4 kblk16)
#define NCHUNK (KSLICE / KC)  // 8
#define NT 64
#define NTILES (NH / NT)      // 32
#define NTHREADS 512
#define NKB16 (NH / 16)       // 128 k-blocks of 16
// smem map (u32): A buf0 [0,8192) | A buf1 [8192,16384) | Whi [16384,32768) | Wlo [32768,49152)
#define ABUF_U32 8192
#define WHI_OFF 16384
#define WLO_OFF 32768
#define SMEM_BYTES (49152 * 4)   // 196608

// ---------------- device scratch ----------------
__device__ float    g_xin[(size_t)T_STEPS * B * NH];   // x @ x2h, [t*B+b][n]
// W fragment-packed bf16x2: [nblk(256)][kblk16(128)][lane(32)][2]
__device__ uint32_t g_Whi[(size_t)(NH / 8) * NKB16 * 64];
__device__ uint32_t g_Wlo[(size_t)(NH / 8) * NKB16 * 64];
// A fragment-packed bf16x2: [mblk(8)][kblk16(128)][lane(32)][4], ping-pong
__device__ uint32_t g_Ahi[2][(size_t)8 * NKB16 * 128];
__device__ uint32_t g_Alo[2][(size_t)8 * NKB16 * 128];
__device__ float    g_hz[(size_t)B * PORT];            // hz state [b][j]
__device__ float    g_part[2][(size_t)SPLITK * B * NH];// split-K partials, step-parity x [kb][b][n]
__device__ int      g_cnt[NTILES];                     // per-ntile GEMM arrival counters (monotonic)
__device__ int      g_epn[NTILES];                     // per-ntile epilogue-done counters (monotonic, +2/step)

// ---------------- helpers ----------------
__device__ __forceinline__ uint32_t smem_u32(const void* p) {
    uint32_t a;
    asm("{ .reg .u64 t; cvta.to.shared.u64 t, %1; cvt.u32.u64 %0, t; }" : "=r"(a) : "l"(p));
    return a;
}
__device__ __forceinline__ float bfr(float x) {
    return __bfloat162float(__float2bfloat16_rn(x));
}
__device__ __forceinline__ uint32_t bf2(float a, float b) {
    __nv_bfloat162 t = __floats2bfloat162_rn(a, b);
    return *(uint32_t*)&t;
}
__device__ __forceinline__ void cpa16(uint32_t dst, const void* src) {
    asm volatile("cp.async.ca.shared.global [%0], [%1], 16;" :: "r"(dst), "l"(src));
}
#define CP_COMMIT() asm volatile("cp.async.commit_group;" ::: "memory")
#define CP_WAIT(n)  asm volatile("cp.async.wait_group %0;" :: "n"(n) : "memory")

__device__ __forceinline__ void mma_bf16(float* c, const uint32_t* a, const uint32_t* b) {
    asm volatile(
        "mma.sync.aligned.m16n8k16.row.col.f32.bf16.bf16.f32 "
        "{%0,%1,%2,%3}, {%4,%5,%6,%7}, {%8,%9}, {%0,%1,%2,%3};"
        : "+f"(c[0]), "+f"(c[1]), "+f"(c[2]), "+f"(c[3])
        : "r"(a[0]), "r"(a[1]), "r"(a[2]), "r"(a[3]), "r"(b[0]), "r"(b[1]));
}

// ---------------- init (zeroes counters each graph replay) -------------------
__global__ void init_kernel() {
    int i = blockIdx.x * blockDim.x + threadIdx.x;
    if (i < 8 * NKB16 * 128) { g_Ahi[0][i] = 0u; g_Alo[0][i] = 0u; }
    if (i < B * PORT) g_hz[i] = 0.0f;
    if (i < NTILES) { g_cnt[i] = 0; g_epn[i] = 0; }
}

// ---------------- h2h -> fragment-packed bf16 hi/lo W (one-time) -------------
__global__ void prep_kernel(const float* __restrict__ h2h) {
    __shared__ float s[32][65];   // [k][n]
    const int tid = threadIdx.x;
    const int n0 = blockIdx.x * 64, k0 = blockIdx.y * 32;
    for (int j = 0; j < 4; j++) {
        int idx = tid + j * 512;
        int kl = idx >> 6, nl = idx & 63;
        s[kl][nl] = h2h[(size_t)(k0 + kl) * NH + n0 + nl];
    }
    __syncthreads();
    const int fb = tid >> 5, lane = tid & 31;
    const int nb = fb >> 1, kb2 = fb & 1;
    const int n_l = nb * 8 + (lane >> 2);
    const int k_l = kb2 * 16 + (lane & 3) * 2;
    float v0 = s[k_l][n_l],     v1 = s[k_l + 1][n_l];
    float v8 = s[k_l + 8][n_l], v9 = s[k_l + 9][n_l];
    float h0 = bfr(v0), h1 = bfr(v1), h8 = bfr(v8), h9 = bfr(v9);
    size_t base = ((size_t)((n0 >> 3) + nb) * NKB16 + (k0 >> 4) + kb2) * 64 + lane * 2;
    *(uint2*)&g_Whi[base] = make_uint2(bf2(h0, h1), bf2(h8, h9));
    *(uint2*)&g_Wlo[base] = make_uint2(bf2(v0 - h0, v1 - h1), bf2(v8 - h8, v9 - h9));
}

// ---------------- xin = x @ x2h for all timesteps (one-time) -----------------
__global__ void xin_kernel(const float* __restrict__ x, const float* __restrict__ x2h) {
    __shared__ float sx[64][NI];
    const int tid = threadIdx.x;
    const int r0 = blockIdx.x * 64;
    const int n = blockIdx.y * 256 + tid;
    for (int s = tid; s < 64 * NI; s += 256) {
        int r = s >> 5, i = s & 31;
        int R = r0 + r;
        int tt = R >> 7, bb = R & 127;
        sx[r][i] = x[((size_t)bb * T_STEPS + tt) * NI + i];
    }
    __syncthreads();
    float acc[64];
#pragma unroll
    for (int r = 0; r < 64; r++) acc[r] = 0.0f;
#pragma unroll
    for (int i = 0; i < NI; i++) {
        float w = x2h[(size_t)i * NH + n];
#pragma unroll
        for (int r = 0; r < 64; r++) acc[r] = fmaf(sx[r][i], w, acc[r]);
    }
#pragma unroll
    for (int r = 0; r < 64; r++)
        g_xin[(size_t)(r0 + r) * NH + n] = acc[r];
}

// ---------------- persistent kernel: all 200 steps, dataflow-synced ----------
// grid (32, 4) = 128 CTAs (all resident), 512 threads.
// W hi/lo resident in smem; A double-buffered per chunk (KC=64).
__global__ void __launch_bounds__(NTHREADS, 1) step_kernel(
    const float* __restrict__ gamma, const float* __restrict__ eps,
    float* __restrict__ out)
{
    extern __shared__ uint32_t smu[];
    __shared__ int s_rank;

    const int tid = threadIdx.x;
    const int warp = tid >> 5, lane = tid & 31;
    const int warpM = warp >> 2, warpN = warp & 3;
    const int ntile = blockIdx.x, kb = blockIdx.y;
    const int n0 = ntile * NT;
    const int kb16 = kb * (KSLICE / 16);     // first kblk16 of this CTA (kb*32)

    float* out_hy  = out;
    float* out_hz  = out + (size_t)T_STEPS * B * NH;
    float* out_hyu = out_hz + (size_t)T_STEPS * B * PORT;
    float* out_spk = out_hyu + (size_t)T_STEPS * B * PORT;

    // ---- one-time W residency load ----
    {
#pragma unroll
        for (int it = 0; it < 8; it++) {
            int i = tid + it * NTHREADS;           // 0..4095
            int piece = i >> 4, j = i & 15;        // 256 pieces x 16 cps
            int nblk = piece >> 5, kblk = piece & 31;
            size_t gsrc = ((size_t)((n0 >> 3) + nblk) * NKB16 + kb16 + kblk) * 64 + j * 4;
            cpa16(smem_u32(smu + WHI_OFF + piece * 64 + j * 4), g_Whi + gsrc);
            cpa16(smem_u32(smu + WLO_OFF + piece * 64 + j * 4), g_Wlo + gsrc);
        }
        CP_COMMIT(); CP_WAIT(0);
        __syncthreads();
    }

    const bool harm = (n0 < PORT);
    const int l16 = lane & 15, lh = lane >> 4;
    const int nl4 = l16 * 4;
    const int n4 = n0 + nl4;
    float4 gm = make_float4(0, 0, 0, 0), epv = make_float4(0, 0, 0, 0);
    if (harm) { gm = *(const float4*)&gamma[n4]; epv = *(const float4*)&eps[n4]; }

    for (int t = 0; t < T_STEPS; t++) {
        const int src = t & 1, dst = src ^ 1;
        const int par = t & 1;
        const uint32_t* __restrict__ Ahi = g_Ahi[src];
        const uint32_t* __restrict__ Alo = g_Alo[src];
        float* __restrict__ part = g_part[par];

        // gate chunk c: producer ntile (kb*8+c) must have finished epilogue t-1
        auto gate = [&](int c) {
            if (tid == 0) {
                const int dep = kb * 8 + c;
                while (((volatile int*)g_epn)[dep] < 2 * t) {}
            }
            __syncthreads();
            __threadfence();   // acquire for A[src] data behind the flag
        };

        // ---- cp.async stage of one A chunk (4 kblk16) into buf (c & 1) ----
        auto issueA = [&](int c) {
            uint32_t* bb = smu + (c & 1) * ABUF_U32;
            const int kc = kb16 + c * 4;
#pragma unroll
            for (int it = 0; it < 2; it++) {
                int i = tid + it * NTHREADS;
                int piece = i >> 5, j = i & 31;
                int mblk = piece >> 2, kk = piece & 3;
                size_t gsrc = ((size_t)mblk * NKB16 + kc + kk) * 128 + j * 4;
                cpa16(smem_u32(bb + piece * 128 + j * 4), Ahi + gsrc);
                cpa16(smem_u32(bb + 4096 + piece * 128 + j * 4), Alo + gsrc);
            }
        };

        float C[2][2][4];
#pragma unroll
        for (int mi = 0; mi < 2; mi++)
#pragma unroll
            for (int ni = 0; ni < 2; ni++)
#pragma unroll
                for (int q = 0; q < 4; q++) C[mi][ni][q] = 0.0f;

        gate(0);
        issueA(0); CP_COMMIT();
        for (int c = 0; c < NCHUNK; c++) {
            if (c < NCHUNK - 1) { gate(c + 1); issueA(c + 1); CP_COMMIT(); CP_WAIT(1); }
            else                { CP_WAIT(0); }
            __syncthreads();
            const uint32_t* tAhi = smu + (c & 1) * ABUF_U32;
            const uint32_t* tAlo = tAhi + 4096;

#pragma unroll
            for (int ks = 0; ks < 4; ks++) {
                uint32_t a[2][4], bh[2][2], bl[2][2];
#pragma unroll
                for (int mi = 0; mi < 2; mi++) {
                    uint4 v = *(const uint4*)&tAhi[((warpM * 2 + mi) * 4 + ks) * 128 + lane * 4];
                    a[mi][0] = v.x; a[mi][1] = v.y; a[mi][2] = v.z; a[mi][3] = v.w;
                }
#pragma unroll
                for (int ni = 0; ni < 2; ni++) {
                    int woff = ((warpN * 2 + ni) * 32 + c * 4 + ks) * 64 + lane * 2;
                    uint2 h = *(const uint2*)&smu[WHI_OFF + woff];
                    uint2 l = *(const uint2*)&smu[WLO_OFF + woff];
                    bh[ni][0] = h.x; bh[ni][1] = h.y;
                    bl[ni][0] = l.x; bl[ni][1] = l.y;
                }
#pragma unroll
                for (int mi = 0; mi < 2; mi++)
#pragma unroll
                    for (int ni = 0; ni < 2; ni++) {
                        mma_bf16(C[mi][ni], a[mi], bh[ni]);   // Ahi * Whi
                        mma_bf16(C[mi][ni], a[mi], bl[ni]);   // Ahi * Wlo
                    }
#pragma unroll
                for (int mi = 0; mi < 2; mi++) {
                    uint4 v = *(const uint4*)&tAlo[((warpM * 2 + mi) * 4 + ks) * 128 + lane * 4];
                    a[mi][0] = v.x; a[mi][1] = v.y; a[mi][2] = v.z; a[mi][3] = v.w;
                }
#pragma unroll
                for (int mi = 0; mi < 2; mi++)
#pragma unroll
                    for (int ni = 0; ni < 2; ni++)
                        mma_bf16(C[mi][ni], a[mi], bh[ni]);   // Alo * Whi
            }
            __syncthreads();
        }

        // ---- write split-K partials (step-parity buffer) ----
        const int r = lane >> 2, cc = lane & 3;
#pragma unroll
        for (int mi = 0; mi < 2; mi++)
#pragma unroll
            for (int ni = 0; ni < 2; ni++) {
                int row = warpM * 32 + mi * 16 + r;
                int col = n0 + warpN * 16 + ni * 8 + cc * 2;
                float2 v0 = make_float2(C[mi][ni][0], C[mi][ni][1]);
                float2 v1 = make_float2(C[mi][ni][2], C[mi][ni][3]);
                *(float2*)&part[((size_t)kb * B + row) * NH + col]     = v0;
                *(float2*)&part[((size_t)kb * B + row + 8) * NH + col] = v1;
            }

        // ---- arrival rank (monotonic); last TWO arrivers split the epilogue --
        __threadfence();
        __syncthreads();
        if (tid == 0) s_rank = atomicAdd(&g_cnt[ntile], 1);
        __syncthreads();
        const int rank = s_rank - SPLITK * t;

        if (rank >= SPLITK - 2) {
            const int half = (rank == SPLITK - 1) ? 1 : 0;
            if (rank == SPLITK - 2) {
                if (tid == 0) {
                    while (((volatile int*)g_cnt)[ntile] < SPLITK * (t + 1)) {}
                }
                __syncthreads();
            }
            __threadfence();   // acquire: order partial reads after arrivals

            // ---- fused epilogue: rows [half*64, half*64+64) ------------------
            float (*sV)[68] = (float(*)[68])smu;   // aliases dead A buffers

            const float* old_hy = out_hy + (size_t)(t - 1) * B * NH;

            for (int rr = 0; rr < 2; rr++) {
                int b = half * 64 + rr * 32 + warp * 2 + lh;
                const size_t ob = (size_t)t * B + b;

                float4 pre = make_float4(0, 0, 0, 0);
#pragma unroll
                for (int q = 0; q < SPLITK; q++) {
                    float4 pv = *(const float4*)&part[((size_t)q * B + b) * NH + n4];
                    pre.x += pv.x; pre.y += pv.y; pre.z += pv.z; pre.w += pv.w;
                }
                float4 xv = *(const float4*)&g_xin[((size_t)t * B + b) * NH + n4];
                pre.x += xv.x; pre.y += xv.y; pre.z += xv.z; pre.w += xv.w;

                float4 f;
                f.x = tanhf(pre.x); f.y = tanhf(pre.y);
                f.z = tanhf(pre.z); f.w = tanhf(pre.w);

                float4 old = make_float4(0, 0, 0, 0);
                if (t > 0) old = *(const float4*)&old_hy[(size_t)b * NH + n4];

                float4 newv;
                if (harm) {
                    float4 hzo = *(const float4*)&g_hz[(size_t)b * PORT + n4];
                    float4 hzn;
                    hzn.x = hzo.x + DT * (f.x - gm.x * old.x - epv.x * hzo.x);
                    hzn.y = hzo.y + DT * (f.y - gm.y * old.y - epv.y * hzo.y);
                    hzn.z = hzo.z + DT * (f.z - gm.z * old.z - epv.z * hzo.z);
                    hzn.w = hzo.w + DT * (f.w - gm.w * old.w - epv.w * hzo.w);
                    newv.x = old.x + DT * hzn.x;
                    newv.y = old.y + DT * hzn.y;
                    newv.z = old.z + DT * hzn.z;
                    newv.w = old.w + DT * hzn.w;
                    *(float4*)&out_hy[ob * NH + n4]   = newv;
                    *(float4*)&out_hz[ob * PORT + n4] = hzn;
                    *(float4*)&g_hz[(size_t)b * PORT + n4] = hzn;
                } else {
                    int j4 = n4 - PORT;
                    float4 spk, u;
                    spk.x = (old.x > THRESH) ? 1.0f : 0.0f;
                    spk.y = (old.y > THRESH) ? 1.0f : 0.0f;
                    spk.z = (old.z > THRESH) ? 1.0f : 0.0f;
                    spk.w = (old.w > THRESH) ? 1.0f : 0.0f;
                    u.x = (spk.x > 0.0f) ? 0.0f : old.x;
                    u.y = (spk.y > 0.0f) ? 0.0f : old.y;
                    u.z = (spk.z > 0.0f) ? 0.0f : old.z;
                    u.w = (spk.w > 0.0f) ? 0.0f : old.w;
                    newv.x = u.x + DT * (f.x - u.x);
                    newv.y = u.y + DT * (f.y - u.y);
                    newv.z = u.z + DT * (f.z - u.z);
                    newv.w = u.w + DT * (f.w - u.w);
                    *(float4*)&out_hy[ob * NH + n4]    = newv;
                    *(float4*)&out_hyu[ob * PORT + j4] = newv;
                    *(float4*)&out_spk[ob * PORT + j4] = spk;
                }
                *(float4*)&sV[b][nl4] = newv;
            }
            __syncthreads();

            // ---- packed bf16 hi/lo A writeback: 16 groups this half ---------
            uint32_t* hyhi_d = g_Ahi[dst];
            uint32_t* hylo_d = g_Alo[dst];
            const int fr = lane >> 2, fc = (lane & 3) * 2;
            {
                int grp = half * 16 + warp;
                int mblk = grp >> 2, kl = grp & 3;
                int r0 = mblk * 16 + fr, r1 = r0 + 8;
                int c0 = kl * 16 + fc;
                float v00 = sV[r0][c0], v01 = sV[r0][c0 + 1];
                float v10 = sV[r1][c0], v11 = sV[r1][c0 + 1];
                float v08 = sV[r0][c0 + 8], v09 = sV[r0][c0 + 9];
                float v18 = sV[r1][c0 + 8], v19 = sV[r1][c0 + 9];
                float h00 = bfr(v00), h01 = bfr(v01), h10 = bfr(v10), h11 = bfr(v11);
                float h08 = bfr(v08), h09 = bfr(v09), h18 = bfr(v18), h19 = bfr(v19);
                uint4 hi, lo;
                hi.x = bf2(h00, h01); lo.x = bf2(v00 - h00, v01 - h01);
                hi.y = bf2(h10, h11); lo.y = bf2(v10 - h10, v11 - h11);
                hi.z = bf2(h08, h09); lo.z = bf2(v08 - h08, v09 - h09);
                hi.w = bf2(h18, h19); lo.w = bf2(v18 - h18, v19 - h19);
                size_t goff = ((size_t)mblk * NKB16 + (n0 >> 4) + kl) * 128 + lane * 4;
                *(uint4*)&hyhi_d[goff] = hi;
                *(uint4*)&hylo_d[goff] = lo;
            }
            __threadfence();
            __syncthreads();
            if (tid == 0) atomicAdd(&g_epn[ntile], 1);   // release: A[dst] for this ntile ready
        }
        // no global barrier: next step's chunk gates enforce the dataflow
    }
}

// ---------------- launch ------------------------------------------------------
extern "C" void kernel_launch(void* const* d_in, const int* in_sizes, int n_in,
                              void* d_out, int out_size) {
    (void)in_sizes; (void)n_in; (void)out_size;
    const float* x     = (const float*)d_in[0];
    const float* x2h   = (const float*)d_in[1];
    const float* h2h   = (const float*)d_in[2];
    const float* gamma = (const float*)d_in[3];
    const float* eps   = (const float*)d_in[4];
    float* out = (float*)d_out;

    cudaFuncSetAttribute(step_kernel, cudaFuncAttributeMaxDynamicSharedMemorySize, SMEM_BYTES);

    init_kernel<<<256, 1024>>>();
    prep_kernel<<<dim3(NH / 64, NH / 32), 512>>>(h2h);
    xin_kernel<<<dim3((T_STEPS * B) / 64, NH / 256), 256>>>(x, x2h);
    step_kernel<<<dim3(NTILES, SPLITK), NTHREADS, SMEM_BYTES>>>(gamma, eps, out);
}

// round 14
// speedup vs baseline: 1.3316x; 1.3316x over previous
#include <cuda_runtime.h>
#include <cuda_bf16.h>
#include <math.h>
#include <stdint.h>

#define B 128
#define T_STEPS 200
#define NH 2048
#define NI 32
#define PORT 1024
#define DT 0.042f
#define THRESH 0.5f

#define SPLITK 8
#define KSLICE 256            // K per CTA
#define KC 64                 // K per A smem stage (4 kblk16)
#define NCHUNK (KSLICE / KC)  // 4
#define NT 128
#define NTILES (NH / NT)      // 16
#define NTHREADS 512
#define NKB16 (NH / 16)       // 128 k-blocks of 16
// smem map (u32): A buf0 [0,8192) | A buf1 [8192,16384) | Whi [16384,32768) | Wlo [32768,49152)
#define ABUF_U32 8192
#define WHI_OFF 16384
#define WLO_OFF 32768
#define SMEM_BYTES (49152 * 4)   // 196608

// ---------------- device scratch ----------------
__device__ float    g_xin[(size_t)T_STEPS * B * NH];   // x @ x2h, [t*B+b][n]
// W fragment-packed bf16x2: [nblk(256)][kblk16(128)][lane(32)][2]
__device__ uint32_t g_Whi[(size_t)(NH / 8) * NKB16 * 64];
__device__ uint32_t g_Wlo[(size_t)(NH / 8) * NKB16 * 64];
// A fragment-packed bf16x2: [mblk(8)][kblk16(128)][lane(32)][4], ping-pong
__device__ uint32_t g_Ahi[2][(size_t)8 * NKB16 * 128];
__device__ uint32_t g_Alo[2][(size_t)8 * NKB16 * 128];
__device__ float    g_hz[(size_t)B * PORT];            // hz state [b][j]
__device__ float    g_part[(size_t)SPLITK * B * NH];   // split-K partials [kb][b][n]
__device__ int      g_cnt[NTILES];                     // per-ntile GEMM arrival counters (monotonic)
__device__ int      g_ep;                              // epilogue-done counter (monotonic, 64/step)

// ---------------- helpers ----------------
__device__ __forceinline__ uint32_t smem_u32(const void* p) {
    uint32_t a;
    asm("{ .reg .u64 t; cvta.to.shared.u64 t, %1; cvt.u32.u64 %0, t; }" : "=r"(a) : "l"(p));
    return a;
}
__device__ __forceinline__ float bfr(float x) {
    return __bfloat162float(__float2bfloat16_rn(x));
}
__device__ __forceinline__ uint32_t bf2(float a, float b) {
    __nv_bfloat162 t = __floats2bfloat162_rn(a, b);
    return *(uint32_t*)&t;
}
__device__ __forceinline__ void cpa16(uint32_t dst, const void* src) {
    asm volatile("cp.async.ca.shared.global [%0], [%1], 16;" :: "r"(dst), "l"(src));
}
#define CP_COMMIT() asm volatile("cp.async.commit_group;" ::: "memory")
#define CP_WAIT(n)  asm volatile("cp.async.wait_group %0;" :: "n"(n) : "memory")

__device__ __forceinline__ void mma_bf16(float* c, const uint32_t* a, const uint32_t* b) {
    asm volatile(
        "mma.sync.aligned.m16n8k16.row.col.f32.bf16.bf16.f32 "
        "{%0,%1,%2,%3}, {%4,%5,%6,%7}, {%8,%9}, {%0,%1,%2,%3};"
        : "+f"(c[0]), "+f"(c[1]), "+f"(c[2]), "+f"(c[3])
        : "r"(a[0]), "r"(a[1]), "r"(a[2]), "r"(a[3]), "r"(b[0]), "r"(b[1]));
}

// ---------------- init (zeroes counters each graph replay) -------------------
__global__ void init_kernel() {
    int i = blockIdx.x * blockDim.x + threadIdx.x;
    if (i < 8 * NKB16 * 128) { g_Ahi[0][i] = 0u; g_Alo[0][i] = 0u; }
    if (i < B * PORT) g_hz[i] = 0.0f;
    if (i < NTILES) g_cnt[i] = 0;
    if (i == 0) g_ep = 0;
}

// ---------------- h2h -> fragment-packed bf16 hi/lo W (one-time) -------------
__global__ void prep_kernel(const float* __restrict__ h2h) {
    __shared__ float s[32][65];   // [k][n]
    const int tid = threadIdx.x;
    const int n0 = blockIdx.x * 64, k0 = blockIdx.y * 32;
    for (int j = 0; j < 4; j++) {
        int idx = tid + j * 512;
        int kl = idx >> 6, nl = idx & 63;
        s[kl][nl] = h2h[(size_t)(k0 + kl) * NH + n0 + nl];
    }
    __syncthreads();
    const int fb = tid >> 5, lane = tid & 31;
    const int nb = fb >> 1, kb2 = fb & 1;
    const int n_l = nb * 8 + (lane >> 2);
    const int k_l = kb2 * 16 + (lane & 3) * 2;
    float v0 = s[k_l][n_l],     v1 = s[k_l + 1][n_l];
    float v8 = s[k_l + 8][n_l], v9 = s[k_l + 9][n_l];
    float h0 = bfr(v0), h1 = bfr(v1), h8 = bfr(v8), h9 = bfr(v9);
    size_t base = ((size_t)((n0 >> 3) + nb) * NKB16 + (k0 >> 4) + kb2) * 64 + lane * 2;
    *(uint2*)&g_Whi[base] = make_uint2(bf2(h0, h1), bf2(h8, h9));
    *(uint2*)&g_Wlo[base] = make_uint2(bf2(v0 - h0, v1 - h1), bf2(v8 - h8, v9 - h9));
}

// ---------------- xin = x @ x2h for all timesteps (one-time) -----------------
__global__ void xin_kernel(const float* __restrict__ x, const float* __restrict__ x2h) {
    __shared__ float sx[64][NI];
    const int tid = threadIdx.x;
    const int r0 = blockIdx.x * 64;
    const int n = blockIdx.y * 256 + tid;
    for (int s = tid; s < 64 * NI; s += 256) {
        int r = s >> 5, i = s & 31;
        int R = r0 + r;
        int tt = R >> 7, bb = R & 127;
        sx[r][i] = x[((size_t)bb * T_STEPS + tt) * NI + i];
    }
    __syncthreads();
    float acc[64];
#pragma unroll
    for (int r = 0; r < 64; r++) acc[r] = 0.0f;
#pragma unroll
    for (int i = 0; i < NI; i++) {
        float w = x2h[(size_t)i * NH + n];
#pragma unroll
        for (int r = 0; r < 64; r++) acc[r] = fmaf(sx[r][i], w, acc[r]);
    }
#pragma unroll
    for (int r = 0; r < 64; r++)
        g_xin[(size_t)(r0 + r) * NH + n] = acc[r];
}

// ---------------- persistent kernel: all 200 steps ---------------------------
// grid (16, 8) = 128 CTAs (all resident), 512 threads.
// CTA tile 128(M) x 128(N) x 256(K); warp grid 4x4, warp tile 32x32.
// W hi/lo resident in smem; A double-buffered per chunk (KC=64).
__global__ void __launch_bounds__(NTHREADS, 1) step_kernel(
    const float* __restrict__ gamma, const float* __restrict__ eps,
    float* __restrict__ out)
{
    extern __shared__ uint32_t smu[];
    __shared__ int s_rank;

    const int tid = threadIdx.x;
    const int warp = tid >> 5, lane = tid & 31;
    const int warpM = warp >> 2, warpN = warp & 3;
    const int ntile = blockIdx.x, kb = blockIdx.y;
    const int n0 = ntile * NT;
    const int kb16 = kb * (KSLICE / 16);     // first kblk16 of this CTA (kb*16)

    float* out_hy  = out;
    float* out_hz  = out + (size_t)T_STEPS * B * NH;
    float* out_hyu = out_hz + (size_t)T_STEPS * B * PORT;
    float* out_spk = out_hyu + (size_t)T_STEPS * B * PORT;

    // ---- one-time W residency load: 16 nblk x 16 kblk x 64 u32, hi+lo -------
    {
#pragma unroll
        for (int it = 0; it < 8; it++) {
            int i = tid + it * NTHREADS;           // 0..4095
            int piece = i >> 4, j = i & 15;        // 256 pieces x 16 cps
            int nblk = piece >> 4, kblk = piece & 15;
            size_t gsrc = ((size_t)((n0 >> 3) + nblk) * NKB16 + kb16 + kblk) * 64 + j * 4;
            cpa16(smem_u32(smu + WHI_OFF + piece * 64 + j * 4), g_Whi + gsrc);
            cpa16(smem_u32(smu + WLO_OFF + piece * 64 + j * 4), g_Wlo + gsrc);
        }
        CP_COMMIT(); CP_WAIT(0);
        __syncthreads();
    }

    const bool harm = (n0 < PORT);
    const int nl4 = lane * 4;
    const int n4 = n0 + nl4;
    float4 gm = make_float4(0, 0, 0, 0), epv = make_float4(0, 0, 0, 0);
    if (harm) { gm = *(const float4*)&gamma[n4]; epv = *(const float4*)&eps[n4]; }

    for (int t = 0; t < T_STEPS; t++) {
        const int src = t & 1, dst = src ^ 1;
        const uint32_t* __restrict__ Ahi = g_Ahi[src];
        const uint32_t* __restrict__ Alo = g_Alo[src];

        // ---- cp.async stage of one A chunk (4 kblk16) into buf (c & 1) ----
        auto issueA = [&](int c) {
            uint32_t* bb = smu + (c & 1) * ABUF_U32;
            const int kc = kb16 + c * 4;
#pragma unroll
            for (int it = 0; it < 2; it++) {
                int i = tid + it * NTHREADS;
                int piece = i >> 5, j = i & 31;
                int mblk = piece >> 2, kk = piece & 3;
                size_t gsrc = ((size_t)mblk * NKB16 + kc + kk) * 128 + j * 4;
                cpa16(smem_u32(bb + piece * 128 + j * 4), Ahi + gsrc);
                cpa16(smem_u32(bb + 4096 + piece * 128 + j * 4), Alo + gsrc);
            }
        };

        float C[2][4][4];
#pragma unroll
        for (int mi = 0; mi < 2; mi++)
#pragma unroll
            for (int ni = 0; ni < 4; ni++)
#pragma unroll
                for (int q = 0; q < 4; q++) C[mi][ni][q] = 0.0f;

        issueA(0); CP_COMMIT();
        for (int c = 0; c < NCHUNK; c++) {
            if (c < NCHUNK - 1) { issueA(c + 1); CP_COMMIT(); CP_WAIT(1); }
            else                { CP_WAIT(0); }
            __syncthreads();
            const uint32_t* tAhi = smu + (c & 1) * ABUF_U32;
            const uint32_t* tAlo = tAhi + 4096;

#pragma unroll
            for (int ks = 0; ks < 4; ks++) {
                uint32_t a[2][4], bh[4][2], bl[4][2];
#pragma unroll
                for (int mi = 0; mi < 2; mi++) {
                    uint4 v = *(const uint4*)&tAhi[((warpM * 2 + mi) * 4 + ks) * 128 + lane * 4];
                    a[mi][0] = v.x; a[mi][1] = v.y; a[mi][2] = v.z; a[mi][3] = v.w;
                }
#pragma unroll
                for (int ni = 0; ni < 4; ni++) {
                    int woff = ((warpN * 4 + ni) * 16 + c * 4 + ks) * 64 + lane * 2;
                    uint2 h = *(const uint2*)&smu[WHI_OFF + woff];
                    uint2 l = *(const uint2*)&smu[WLO_OFF + woff];
                    bh[ni][0] = h.x; bh[ni][1] = h.y;
                    bl[ni][0] = l.x; bl[ni][1] = l.y;
                }
#pragma unroll
                for (int mi = 0; mi < 2; mi++)
#pragma unroll
                    for (int ni = 0; ni < 4; ni++) {
                        mma_bf16(C[mi][ni], a[mi], bh[ni]);   // Ahi * Whi
                        mma_bf16(C[mi][ni], a[mi], bl[ni]);   // Ahi * Wlo
                    }
#pragma unroll
                for (int mi = 0; mi < 2; mi++) {
                    uint4 v = *(const uint4*)&tAlo[((warpM * 2 + mi) * 4 + ks) * 128 + lane * 4];
                    a[mi][0] = v.x; a[mi][1] = v.y; a[mi][2] = v.z; a[mi][3] = v.w;
                }
#pragma unroll
                for (int mi = 0; mi < 2; mi++)
#pragma unroll
                    for (int ni = 0; ni < 4; ni++)
                        mma_bf16(C[mi][ni], a[mi], bh[ni]);   // Alo * Whi
            }
            __syncthreads();
        }

        // ---- write split-K partials ----
        const int r = lane >> 2, cc = lane & 3;
#pragma unroll
        for (int mi = 0; mi < 2; mi++)
#pragma unroll
            for (int ni = 0; ni < 4; ni++) {
                int row = warpM * 32 + mi * 16 + r;
                int col = n0 + warpN * 32 + ni * 8 + cc * 2;
                float2 v0 = make_float2(C[mi][ni][0], C[mi][ni][1]);
                float2 v1 = make_float2(C[mi][ni][2], C[mi][ni][3]);
                *(float2*)&g_part[((size_t)kb * B + row) * NH + col]     = v0;
                *(float2*)&g_part[((size_t)kb * B + row + 8) * NH + col] = v1;
            }

        // ---- arrival rank (monotonic); last FOUR arrivers split the epilogue -
        __threadfence();
        __syncthreads();
        if (tid == 0) s_rank = atomicAdd(&g_cnt[ntile], 1);
        __syncthreads();
        const int rank = s_rank - SPLITK * t;

        if (rank >= SPLITK - 4) {
            const int q4 = rank - (SPLITK - 4);   // 0..3: this CTA's row quarter
            if (tid == 0) {
                while (((volatile int*)g_cnt)[ntile] < SPLITK * (t + 1)) {}
            }
            __syncthreads();
            __threadfence();   // acquire: order partial reads after arrivals

            // ---- fused epilogue: rows [q4*32, q4*32+32) x 128 n --------------
            float (*sV)[132] = (float(*)[132])smu;   // local staging [32][132]

            const float* old_hy = out_hy + (size_t)(t - 1) * B * NH;

            for (int rr = 0; rr < 2; rr++) {
                int lb = rr * 16 + warp;          // local row 0..31
                int b = q4 * 32 + lb;
                const size_t ob = (size_t)t * B + b;

                float4 pre = make_float4(0, 0, 0, 0);
#pragma unroll
                for (int q = 0; q < SPLITK; q++) {
                    float4 pv = *(const float4*)&g_part[((size_t)q * B + b) * NH + n4];
                    pre.x += pv.x; pre.y += pv.y; pre.z += pv.z; pre.w += pv.w;
                }
                float4 xv = *(const float4*)&g_xin[((size_t)t * B + b) * NH + n4];
                pre.x += xv.x; pre.y += xv.y; pre.z += xv.z; pre.w += xv.w;

                float4 f;
                f.x = tanhf(pre.x); f.y = tanhf(pre.y);
                f.z = tanhf(pre.z); f.w = tanhf(pre.w);

                float4 old = make_float4(0, 0, 0, 0);
                if (t > 0) old = *(const float4*)&old_hy[(size_t)b * NH + n4];

                float4 newv;
                if (harm) {
                    float4 hzo = *(const float4*)&g_hz[(size_t)b * PORT + n4];
                    float4 hzn;
                    hzn.x = hzo.x + DT * (f.x - gm.x * old.x - epv.x * hzo.x);
                    hzn.y = hzo.y + DT * (f.y - gm.y * old.y - epv.y * hzo.y);
                    hzn.z = hzo.z + DT * (f.z - gm.z * old.z - epv.z * hzo.z);
                    hzn.w = hzo.w + DT * (f.w - gm.w * old.w - epv.w * hzo.w);
                    newv.x = old.x + DT * hzn.x;
                    newv.y = old.y + DT * hzn.y;
                    newv.z = old.z + DT * hzn.z;
                    newv.w = old.w + DT * hzn.w;
                    *(float4*)&out_hy[ob * NH + n4]   = newv;
                    *(float4*)&out_hz[ob * PORT + n4] = hzn;
                    *(float4*)&g_hz[(size_t)b * PORT + n4] = hzn;
                } else {
                    int j4 = n4 - PORT;
                    float4 spk, u;
                    spk.x = (old.x > THRESH) ? 1.0f : 0.0f;
                    spk.y = (old.y > THRESH) ? 1.0f : 0.0f;
                    spk.z = (old.z > THRESH) ? 1.0f : 0.0f;
                    spk.w = (old.w > THRESH) ? 1.0f : 0.0f;
                    u.x = (spk.x > 0.0f) ? 0.0f : old.x;
                    u.y = (spk.y > 0.0f) ? 0.0f : old.y;
                    u.z = (spk.z > 0.0f) ? 0.0f : old.z;
                    u.w = (spk.w > 0.0f) ? 0.0f : old.w;
                    newv.x = u.x + DT * (f.x - u.x);
                    newv.y = u.y + DT * (f.y - u.y);
                    newv.z = u.z + DT * (f.z - u.z);
                    newv.w = u.w + DT * (f.w - u.w);
                    *(float4*)&out_hy[ob * NH + n4]    = newv;
                    *(float4*)&out_hyu[ob * PORT + j4] = newv;
                    *(float4*)&out_spk[ob * PORT + j4] = spk;
                }
                *(float4*)&sV[lb][nl4] = newv;
            }
            __syncthreads();

            // ---- packed bf16 hi/lo A writeback: 16 groups (2 mblk x 8 kl) ----
            uint32_t* hyhi_d = g_Ahi[dst];
            uint32_t* hylo_d = g_Alo[dst];
            const int fr = lane >> 2, fc = (lane & 3) * 2;
            {
                int lq = warp >> 3, kl = warp & 7;   // local mblk, local kblk16
                int mblk = q4 * 2 + lq;              // global mblk
                int r0 = lq * 16 + fr, r1 = r0 + 8;  // local sV rows
                int c0 = kl * 16 + fc;
                float v00 = sV[r0][c0], v01 = sV[r0][c0 + 1];
                float v10 = sV[r1][c0], v11 = sV[r1][c0 + 1];
                float v08 = sV[r0][c0 + 8], v09 = sV[r0][c0 + 9];
                float v18 = sV[r1][c0 + 8], v19 = sV[r1][c0 + 9];
                float h00 = bfr(v00), h01 = bfr(v01), h10 = bfr(v10), h11 = bfr(v11);
                float h08 = bfr(v08), h09 = bfr(v09), h18 = bfr(v18), h19 = bfr(v19);
                uint4 hi, lo;
                hi.x = bf2(h00, h01); lo.x = bf2(v00 - h00, v01 - h01);
                hi.y = bf2(h10, h11); lo.y = bf2(v10 - h10, v11 - h11);
                hi.z = bf2(h08, h09); lo.z = bf2(v08 - h08, v09 - h09);
                hi.w = bf2(h18, h19); lo.w = bf2(v18 - h18, v19 - h19);
                size_t goff = ((size_t)mblk * NKB16 + (n0 >> 4) + kl) * 128 + lane * 4;
                *(uint4*)&hyhi_d[goff] = hi;
                *(uint4*)&hylo_d[goff] = lo;
            }
            __threadfence();
            __syncthreads();
            if (tid == 0) atomicAdd(&g_ep, 1);
        }

        // ---- global step barrier: next step needs all epilogues done --------
        if (tid == 0) {
            while (*((volatile int*)&g_ep) < 64 * (t + 1)) {}
        }
        __syncthreads();
        __threadfence();   // acquire for A[dst]/g_part reuse next iteration
    }
}

// ---------------- launch ------------------------------------------------------
extern "C" void kernel_launch(void* const* d_in, const int* in_sizes, int n_in,
                              void* d_out, int out_size) {
    (void)in_sizes; (void)n_in; (void)out_size;
    const float* x     = (const float*)d_in[0];
    const float* x2h   = (const float*)d_in[1];
    const float* h2h   = (const float*)d_in[2];
    const float* gamma = (const float*)d_in[3];
    const float* eps   = (const float*)d_in[4];
    float* out = (float*)d_out;

    cudaFuncSetAttribute(step_kernel, cudaFuncAttributeMaxDynamicSharedMemorySize, SMEM_BYTES);

    init_kernel<<<256, 1024>>>();
    prep_kernel<<<dim3(NH / 64, NH / 32), 512>>>(h2h);
    xin_kernel<<<dim3((T_STEPS * B) / 64, NH / 256), 256>>>(x, x2h);
    step_kernel<<<dim3(NTILES, SPLITK), NTHREADS, SMEM_BYTES>>>(gamma, eps, out);
}

// round 15
// speedup vs baseline: 1.4479x; 1.0874x over previous
#include <cuda_runtime.h>
#include <cuda_bf16.h>
#include <math.h>
#include <stdint.h>

#define B 128
#define T_STEPS 200
#define NH 2048
#define NI 32
#define PORT 1024
#define DT 0.042f
#define THRESH 0.5f

#define SPLITK 8
#define KSLICE 256            // K per CTA
#define KC 64                 // K per A smem stage (4 kblk16)
#define NCHUNK (KSLICE / KC)  // 4
#define NT 128
#define NTILES (NH / NT)      // 16
#define NTHREADS 512
#define NKB16 (NH / 16)       // 128 k-blocks of 16
// smem map (u32): A buf0 [0,8192) | A buf1 [8192,16384) | Whi [16384,32768) | Wlo [32768,49152)
#define ABUF_U32 8192
#define WHI_OFF 16384
#define WLO_OFF 32768
#define SMEM_BYTES (49152 * 4)   // 196608

// ---------------- device scratch ----------------
__device__ float    g_xin[(size_t)T_STEPS * B * NH];   // x @ x2h, [t*B+b][n]
// W fragment-packed bf16x2: [nblk(256)][kblk16(128)][lane(32)][2]
__device__ uint32_t g_Whi[(size_t)(NH / 8) * NKB16 * 64];
__device__ uint32_t g_Wlo[(size_t)(NH / 8) * NKB16 * 64];
// A fragment-packed bf16x2: [mblk(8)][kblk16(128)][lane(32)][4], ping-pong
__device__ uint32_t g_Ahi[2][(size_t)8 * NKB16 * 128];
__device__ uint32_t g_Alo[2][(size_t)8 * NKB16 * 128];
__device__ float    g_hz[(size_t)B * PORT];            // hz state [b][j]
__device__ float    g_part[(size_t)SPLITK * B * NH];   // split-K partials [kb][b][n]
__device__ int      g_cnt[NTILES];                     // per-ntile GEMM arrival counters (monotonic)
__device__ int      g_ep;                              // epilogue-done counter (monotonic, 128/step)

// ---------------- helpers ----------------
__device__ __forceinline__ uint32_t smem_u32(const void* p) {
    uint32_t a;
    asm("{ .reg .u64 t; cvta.to.shared.u64 t, %1; cvt.u32.u64 %0, t; }" : "=r"(a) : "l"(p));
    return a;
}
__device__ __forceinline__ float bfr(float x) {
    return __bfloat162float(__float2bfloat16_rn(x));
}
__device__ __forceinline__ uint32_t bf2(float a, float b) {
    __nv_bfloat162 t = __floats2bfloat162_rn(a, b);
    return *(uint32_t*)&t;
}
__device__ __forceinline__ void cpa16(uint32_t dst, const void* src) {
    asm volatile("cp.async.ca.shared.global [%0], [%1], 16;" :: "r"(dst), "l"(src));
}
#define CP_COMMIT() asm volatile("cp.async.commit_group;" ::: "memory")
#define CP_WAIT(n)  asm volatile("cp.async.wait_group %0;" :: "n"(n) : "memory")

__device__ __forceinline__ void mma_bf16(float* c, const uint32_t* a, const uint32_t* b) {
    asm volatile(
        "mma.sync.aligned.m16n8k16.row.col.f32.bf16.bf16.f32 "
        "{%0,%1,%2,%3}, {%4,%5,%6,%7}, {%8,%9}, {%0,%1,%2,%3};"
        : "+f"(c[0]), "+f"(c[1]), "+f"(c[2]), "+f"(c[3])
        : "r"(a[0]), "r"(a[1]), "r"(a[2]), "r"(a[3]), "r"(b[0]), "r"(b[1]));
}

// ---------------- init (zeroes counters each graph replay) -------------------
__global__ void init_kernel() {
    int i = blockIdx.x * blockDim.x + threadIdx.x;
    if (i < 8 * NKB16 * 128) { g_Ahi[0][i] = 0u; g_Alo[0][i] = 0u; }
    if (i < B * PORT) g_hz[i] = 0.0f;
    if (i < NTILES) g_cnt[i] = 0;
    if (i == 0) g_ep = 0;
}

// ---------------- h2h -> fragment-packed bf16 hi/lo W (one-time) -------------
__global__ void prep_kernel(const float* __restrict__ h2h) {
    __shared__ float s[32][65];   // [k][n]
    const int tid = threadIdx.x;
    const int n0 = blockIdx.x * 64, k0 = blockIdx.y * 32;
    for (int j = 0; j < 4; j++) {
        int idx = tid + j * 512;
        int kl = idx >> 6, nl = idx & 63;
        s[kl][nl] = h2h[(size_t)(k0 + kl) * NH + n0 + nl];
    }
    __syncthreads();
    const int fb = tid >> 5, lane = tid & 31;
    const int nb = fb >> 1, kb2 = fb & 1;
    const int n_l = nb * 8 + (lane >> 2);
    const int k_l = kb2 * 16 + (lane & 3) * 2;
    float v0 = s[k_l][n_l],     v1 = s[k_l + 1][n_l];
    float v8 = s[k_l + 8][n_l], v9 = s[k_l + 9][n_l];
    float h0 = bfr(v0), h1 = bfr(v1), h8 = bfr(v8), h9 = bfr(v9);
    size_t base = ((size_t)((n0 >> 3) + nb) * NKB16 + (k0 >> 4) + kb2) * 64 + lane * 2;
    *(uint2*)&g_Whi[base] = make_uint2(bf2(h0, h1), bf2(h8, h9));
    *(uint2*)&g_Wlo[base] = make_uint2(bf2(v0 - h0, v1 - h1), bf2(v8 - h8, v9 - h9));
}

// ---------------- xin = x @ x2h for all timesteps (one-time) -----------------
__global__ void xin_kernel(const float* __restrict__ x, const float* __restrict__ x2h) {
    __shared__ float sx[64][NI];
    const int tid = threadIdx.x;
    const int r0 = blockIdx.x * 64;
    const int n = blockIdx.y * 256 + tid;
    for (int s = tid; s < 64 * NI; s += 256) {
        int r = s >> 5, i = s & 31;
        int R = r0 + r;
        int tt = R >> 7, bb = R & 127;
        sx[r][i] = x[((size_t)bb * T_STEPS + tt) * NI + i];
    }
    __syncthreads();
    float acc[64];
#pragma unroll
    for (int r = 0; r < 64; r++) acc[r] = 0.0f;
#pragma unroll
    for (int i = 0; i < NI; i++) {
        float w = x2h[(size_t)i * NH + n];
#pragma unroll
        for (int r = 0; r < 64; r++) acc[r] = fmaf(sx[r][i], w, acc[r]);
    }
#pragma unroll
    for (int r = 0; r < 64; r++)
        g_xin[(size_t)(r0 + r) * NH + n] = acc[r];
}

// ---------------- persistent kernel: all 200 steps ---------------------------
// grid (16, 8) = 128 CTAs (all resident), 512 threads.
// CTA tile 128(M) x 128(N) x 256(K); warp grid 4x4, warp tile 32x32.
// W hi/lo resident in smem; A double-buffered per chunk (KC=64).
// Epilogue distributed: every CTA handles its own 16 rows (mblk = kb).
__global__ void __launch_bounds__(NTHREADS, 1) step_kernel(
    const float* __restrict__ gamma, const float* __restrict__ eps,
    float* __restrict__ out)
{
    extern __shared__ uint32_t smu[];

    const int tid = threadIdx.x;
    const int warp = tid >> 5, lane = tid & 31;
    const int warpM = warp >> 2, warpN = warp & 3;
    const int ntile = blockIdx.x, kb = blockIdx.y;
    const int n0 = ntile * NT;
    const int kb16 = kb * (KSLICE / 16);     // first kblk16 of this CTA (kb*16)

    float* out_hy  = out;
    float* out_hz  = out + (size_t)T_STEPS * B * NH;
    float* out_hyu = out_hz + (size_t)T_STEPS * B * PORT;
    float* out_spk = out_hyu + (size_t)T_STEPS * B * PORT;

    // ---- one-time W residency load: 16 nblk x 16 kblk x 64 u32, hi+lo -------
    {
#pragma unroll
        for (int it = 0; it < 8; it++) {
            int i = tid + it * NTHREADS;           // 0..4095
            int piece = i >> 4, j = i & 15;        // 256 pieces x 16 cps
            int nblk = piece >> 4, kblk = piece & 15;
            size_t gsrc = ((size_t)((n0 >> 3) + nblk) * NKB16 + kb16 + kblk) * 64 + j * 4;
            cpa16(smem_u32(smu + WHI_OFF + piece * 64 + j * 4), g_Whi + gsrc);
            cpa16(smem_u32(smu + WLO_OFF + piece * 64 + j * 4), g_Wlo + gsrc);
        }
        CP_COMMIT(); CP_WAIT(0);
        __syncthreads();
    }

    const bool harm = (n0 < PORT);
    const int nl4 = lane * 4;
    const int n4 = n0 + nl4;
    float4 gm = make_float4(0, 0, 0, 0), epv = make_float4(0, 0, 0, 0);
    if (harm) { gm = *(const float4*)&gamma[n4]; epv = *(const float4*)&eps[n4]; }

    for (int t = 0; t < T_STEPS; t++) {
        const int src = t & 1, dst = src ^ 1;
        const uint32_t* __restrict__ Ahi = g_Ahi[src];
        const uint32_t* __restrict__ Alo = g_Alo[src];

        // ---- cp.async stage of one A chunk (4 kblk16) into buf (c & 1) ----
        auto issueA = [&](int c) {
            uint32_t* bb = smu + (c & 1) * ABUF_U32;
            const int kc = kb16 + c * 4;
#pragma unroll
            for (int it = 0; it < 2; it++) {
                int i = tid + it * NTHREADS;
                int piece = i >> 5, j = i & 31;
                int mblk = piece >> 2, kk = piece & 3;
                size_t gsrc = ((size_t)mblk * NKB16 + kc + kk) * 128 + j * 4;
                cpa16(smem_u32(bb + piece * 128 + j * 4), Ahi + gsrc);
                cpa16(smem_u32(bb + 4096 + piece * 128 + j * 4), Alo + gsrc);
            }
        };

        float C[2][4][4];
#pragma unroll
        for (int mi = 0; mi < 2; mi++)
#pragma unroll
            for (int ni = 0; ni < 4; ni++)
#pragma unroll
                for (int q = 0; q < 4; q++) C[mi][ni][q] = 0.0f;

        issueA(0); CP_COMMIT();
        for (int c = 0; c < NCHUNK; c++) {
            if (c < NCHUNK - 1) { issueA(c + 1); CP_COMMIT(); CP_WAIT(1); }
            else                { CP_WAIT(0); }
            __syncthreads();
            const uint32_t* tAhi = smu + (c & 1) * ABUF_U32;
            const uint32_t* tAlo = tAhi + 4096;

#pragma unroll
            for (int ks = 0; ks < 4; ks++) {
                uint32_t a[2][4], bh[4][2], bl[4][2];
#pragma unroll
                for (int mi = 0; mi < 2; mi++) {
                    uint4 v = *(const uint4*)&tAhi[((warpM * 2 + mi) * 4 + ks) * 128 + lane * 4];
                    a[mi][0] = v.x; a[mi][1] = v.y; a[mi][2] = v.z; a[mi][3] = v.w;
                }
#pragma unroll
                for (int ni = 0; ni < 4; ni++) {
                    int woff = ((warpN * 4 + ni) * 16 + c * 4 + ks) * 64 + lane * 2;
                    uint2 h = *(const uint2*)&smu[WHI_OFF + woff];
                    uint2 l = *(const uint2*)&smu[WLO_OFF + woff];
                    bh[ni][0] = h.x; bh[ni][1] = h.y;
                    bl[ni][0] = l.x; bl[ni][1] = l.y;
                }
#pragma unroll
                for (int mi = 0; mi < 2; mi++)
#pragma unroll
                    for (int ni = 0; ni < 4; ni++) {
                        mma_bf16(C[mi][ni], a[mi], bh[ni]);   // Ahi * Whi
                        mma_bf16(C[mi][ni], a[mi], bl[ni]);   // Ahi * Wlo
                    }
#pragma unroll
                for (int mi = 0; mi < 2; mi++) {
                    uint4 v = *(const uint4*)&tAlo[((warpM * 2 + mi) * 4 + ks) * 128 + lane * 4];
                    a[mi][0] = v.x; a[mi][1] = v.y; a[mi][2] = v.z; a[mi][3] = v.w;
                }
#pragma unroll
                for (int mi = 0; mi < 2; mi++)
#pragma unroll
                    for (int ni = 0; ni < 4; ni++)
                        mma_bf16(C[mi][ni], a[mi], bh[ni]);   // Alo * Whi
            }
            __syncthreads();
        }

        // ---- write split-K partials ----
        const int r = lane >> 2, cc = lane & 3;
#pragma unroll
        for (int mi = 0; mi < 2; mi++)
#pragma unroll
            for (int ni = 0; ni < 4; ni++) {
                int row = warpM * 32 + mi * 16 + r;
                int col = n0 + warpN * 32 + ni * 8 + cc * 2;
                float2 v0 = make_float2(C[mi][ni][0], C[mi][ni][1]);
                float2 v1 = make_float2(C[mi][ni][2], C[mi][ni][3]);
                *(float2*)&g_part[((size_t)kb * B + row) * NH + col]     = v0;
                *(float2*)&g_part[((size_t)kb * B + row + 8) * NH + col] = v1;
            }

        // ---- per-ntile barrier: all 8 split-K CTAs must arrive ---------------
        __threadfence();
        __syncthreads();
        if (tid == 0) {
            atomicAdd(&g_cnt[ntile], 1);
            while (((volatile int*)g_cnt)[ntile] < SPLITK * (t + 1)) {}
        }
        __syncthreads();
        __threadfence();   // acquire: order partial reads after arrivals

        // ---- distributed epilogue: this CTA handles rows [kb*16, kb*16+16) --
        {
            float (*sV)[132] = (float(*)[132])smu;   // staging [16][132]
            const float* old_hy = out_hy + (size_t)(t - 1) * B * NH;

            const int lb = warp;                 // local row 0..15 (one per warp)
            const int b = kb * 16 + lb;
            const size_t ob = (size_t)t * B + b;

            float4 pre = make_float4(0, 0, 0, 0);
#pragma unroll
            for (int q = 0; q < SPLITK; q++) {
                float4 pv = *(const float4*)&g_part[((size_t)q * B + b) * NH + n4];
                pre.x += pv.x; pre.y += pv.y; pre.z += pv.z; pre.w += pv.w;
            }
            float4 xv = *(const float4*)&g_xin[((size_t)t * B + b) * NH + n4];
            pre.x += xv.x; pre.y += xv.y; pre.z += xv.z; pre.w += xv.w;

            float4 f;
            f.x = tanhf(pre.x); f.y = tanhf(pre.y);
            f.z = tanhf(pre.z); f.w = tanhf(pre.w);

            float4 old = make_float4(0, 0, 0, 0);
            if (t > 0) old = *(const float4*)&old_hy[(size_t)b * NH + n4];

            float4 newv;
            if (harm) {
                float4 hzo = *(const float4*)&g_hz[(size_t)b * PORT + n4];
                float4 hzn;
                hzn.x = hzo.x + DT * (f.x - gm.x * old.x - epv.x * hzo.x);
                hzn.y = hzo.y + DT * (f.y - gm.y * old.y - epv.y * hzo.y);
                hzn.z = hzo.z + DT * (f.z - gm.z * old.z - epv.z * hzo.z);
                hzn.w = hzo.w + DT * (f.w - gm.w * old.w - epv.w * hzo.w);
                newv.x = old.x + DT * hzn.x;
                newv.y = old.y + DT * hzn.y;
                newv.z = old.z + DT * hzn.z;
                newv.w = old.w + DT * hzn.w;
                *(float4*)&out_hy[ob * NH + n4]   = newv;
                *(float4*)&out_hz[ob * PORT + n4] = hzn;
                *(float4*)&g_hz[(size_t)b * PORT + n4] = hzn;
            } else {
                int j4 = n4 - PORT;
                float4 spk, u;
                spk.x = (old.x > THRESH) ? 1.0f : 0.0f;
                spk.y = (old.y > THRESH) ? 1.0f : 0.0f;
                spk.z = (old.z > THRESH) ? 1.0f : 0.0f;
                spk.w = (old.w > THRESH) ? 1.0f : 0.0f;
                u.x = (spk.x > 0.0f) ? 0.0f : old.x;
                u.y = (spk.y > 0.0f) ? 0.0f : old.y;
                u.z = (spk.z > 0.0f) ? 0.0f : old.z;
                u.w = (spk.w > 0.0f) ? 0.0f : old.w;
                newv.x = u.x + DT * (f.x - u.x);
                newv.y = u.y + DT * (f.y - u.y);
                newv.z = u.z + DT * (f.z - u.z);
                newv.w = u.w + DT * (f.w - u.w);
                *(float4*)&out_hy[ob * NH + n4]    = newv;
                *(float4*)&out_hyu[ob * PORT + j4] = newv;
                *(float4*)&out_spk[ob * PORT + j4] = spk;
            }
            *(float4*)&sV[lb][nl4] = newv;
            __syncthreads();

            // ---- packed bf16 hi/lo A writeback: mblk = kb, warps 0..7 --------
            if (warp < 8) {
                uint32_t* hyhi_d = g_Ahi[dst];
                uint32_t* hylo_d = g_Alo[dst];
                const int fr = lane >> 2, fc = (lane & 3) * 2;
                const int kl = warp;             // local kblk16 0..7
                int r0 = fr, r1 = fr + 8;        // local sV rows
                int c0 = kl * 16 + fc;
                float v00 = sV[r0][c0], v01 = sV[r0][c0 + 1];
                float v10 = sV[r1][c0], v11 = sV[r1][c0 + 1];
                float v08 = sV[r0][c0 + 8], v09 = sV[r0][c0 + 9];
                float v18 = sV[r1][c0 + 8], v19 = sV[r1][c0 + 9];
                float h00 = bfr(v00), h01 = bfr(v01), h10 = bfr(v10), h11 = bfr(v11);
                float h08 = bfr(v08), h09 = bfr(v09), h18 = bfr(v18), h19 = bfr(v19);
                uint4 hi, lo;
                hi.x = bf2(h00, h01); lo.x = bf2(v00 - h00, v01 - h01);
                hi.y = bf2(h10, h11); lo.y = bf2(v10 - h10, v11 - h11);
                hi.z = bf2(h08, h09); lo.z = bf2(v08 - h08, v09 - h09);
                hi.w = bf2(h18, h19); lo.w = bf2(v18 - h18, v19 - h19);
                size_t goff = ((size_t)kb * NKB16 + (n0 >> 4) + kl) * 128 + lane * 4;
                *(uint4*)&hyhi_d[goff] = hi;
                *(uint4*)&hylo_d[goff] = lo;
            }
            __threadfence();
            __syncthreads();
            if (tid == 0) atomicAdd(&g_ep, 1);
        }

        // ---- global step barrier: next step needs all epilogues done --------
        if (tid == 0) {
            while (*((volatile int*)&g_ep) < 128 * (t + 1)) {}
        }
        __syncthreads();
        __threadfence();   // acquire for A[dst]/g_part reuse next iteration
    }
}

// ---------------- launch ------------------------------------------------------
extern "C" void kernel_launch(void* const* d_in, const int* in_sizes, int n_in,
                              void* d_out, int out_size) {
    (void)in_sizes; (void)n_in; (void)out_size;
    const float* x     = (const float*)d_in[0];
    const float* x2h   = (const float*)d_in[1];
    const float* h2h   = (const float*)d_in[2];
    const float* gamma = (const float*)d_in[3];
    const float* eps   = (const float*)d_in[4];
    float* out = (float*)d_out;

    cudaFuncSetAttribute(step_kernel, cudaFuncAttributeMaxDynamicSharedMemorySize, SMEM_BYTES);

    init_kernel<<<256, 1024>>>();
    prep_kernel<<<dim3(NH / 64, NH / 32), 512>>>(h2h);
    xin_kernel<<<dim3((T_STEPS * B) / 64, NH / 256), 256>>>(x, x2h);
    step_kernel<<<dim3(NTILES, SPLITK), NTHREADS, SMEM_BYTES>>>(gamma, eps, out);
}

// round 16
// speedup vs baseline: 1.4641x; 1.0112x over previous
#include <cuda_runtime.h>
#include <cuda_bf16.h>
#include <math.h>
#include <stdint.h>

#define B 128
#define T_STEPS 200
#define NH 2048
#define NI 32
#define PORT 1024
#define DT 0.042f
#define THRESH 0.5f

#define SPLITK 8
#define KSLICE 256            // K per CTA
#define KC 64                 // K per A smem stage (4 kblk16)
#define NCHUNK (KSLICE / KC)  // 4
#define NT 128
#define NTILES (NH / NT)      // 16
#define NTHREADS 512
#define NKB16 (NH / 16)       // 128 k-blocks of 16
// smem map (u32): A buf0 [0,8192) | A buf1 [8192,16384) | Whi [16384,32768) | Wlo [32768,49152)
#define ABUF_U32 8192
#define WHI_OFF 16384
#define WLO_OFF 32768
#define SMEM_BYTES (49152 * 4)   // 196608

// ---------------- device scratch ----------------
__device__ float    g_xin[(size_t)T_STEPS * B * NH];   // x @ x2h, [t*B+b][n]
// W fragment-packed bf16x2: [nblk(256)][kblk16(128)][lane(32)][2]
__device__ uint32_t g_Whi[(size_t)(NH / 8) * NKB16 * 64];
__device__ uint32_t g_Wlo[(size_t)(NH / 8) * NKB16 * 64];
// A fragment-packed bf16x2: [mblk(8)][kblk16(128)][lane(32)][4], ping-pong
__device__ uint32_t g_Ahi[2][(size_t)8 * NKB16 * 128];
__device__ uint32_t g_Alo[2][(size_t)8 * NKB16 * 128];
__device__ float    g_hz[(size_t)B * PORT];            // hz state [b][j]
__device__ float    g_part[2][(size_t)SPLITK * B * NH];// split-K partials, step parity
__device__ int      g_cnt[NTILES];                     // per-ntile GEMM arrival counters (monotonic)
__device__ int      g_epn[NTILES];                     // per-ntile epilogue counters (monotonic, +8/step)

// ---------------- helpers ----------------
__device__ __forceinline__ uint32_t smem_u32(const void* p) {
    uint32_t a;
    asm("{ .reg .u64 t; cvta.to.shared.u64 t, %1; cvt.u32.u64 %0, t; }" : "=r"(a) : "l"(p));
    return a;
}
__device__ __forceinline__ float bfr(float x) {
    return __bfloat162float(__float2bfloat16_rn(x));
}
__device__ __forceinline__ uint32_t bf2(float a, float b) {
    __nv_bfloat162 t = __floats2bfloat162_rn(a, b);
    return *(uint32_t*)&t;
}
__device__ __forceinline__ void cpa16(uint32_t dst, const void* src) {
    asm volatile("cp.async.ca.shared.global [%0], [%1], 16;" :: "r"(dst), "l"(src));
}
#define CP_COMMIT() asm volatile("cp.async.commit_group;" ::: "memory")
#define CP_WAIT(n)  asm volatile("cp.async.wait_group %0;" :: "n"(n) : "memory")

__device__ __forceinline__ void mma_bf16(float* c, const uint32_t* a, const uint32_t* b) {
    asm volatile(
        "mma.sync.aligned.m16n8k16.row.col.f32.bf16.bf16.f32 "
        "{%0,%1,%2,%3}, {%4,%5,%6,%7}, {%8,%9}, {%0,%1,%2,%3};"
        : "+f"(c[0]), "+f"(c[1]), "+f"(c[2]), "+f"(c[3])
        : "r"(a[0]), "r"(a[1]), "r"(a[2]), "r"(a[3]), "r"(b[0]), "r"(b[1]));
}

// ---------------- init (zeroes counters each graph replay) -------------------
__global__ void init_kernel() {
    int i = blockIdx.x * blockDim.x + threadIdx.x;
    if (i < 8 * NKB16 * 128) { g_Ahi[0][i] = 0u; g_Alo[0][i] = 0u; }
    if (i < B * PORT) g_hz[i] = 0.0f;
    if (i < NTILES) { g_cnt[i] = 0; g_epn[i] = 0; }
}

// ---------------- h2h -> fragment-packed bf16 hi/lo W (one-time) -------------
__global__ void prep_kernel(const float* __restrict__ h2h) {
    __shared__ float s[32][65];   // [k][n]
    const int tid = threadIdx.x;
    const int n0 = blockIdx.x * 64, k0 = blockIdx.y * 32;
    for (int j = 0; j < 4; j++) {
        int idx = tid + j * 512;
        int kl = idx >> 6, nl = idx & 63;
        s[kl][nl] = h2h[(size_t)(k0 + kl) * NH + n0 + nl];
    }
    __syncthreads();
    const int fb = tid >> 5, lane = tid & 31;
    const int nb = fb >> 1, kb2 = fb & 1;
    const int n_l = nb * 8 + (lane >> 2);
    const int k_l = kb2 * 16 + (lane & 3) * 2;
    float v0 = s[k_l][n_l],     v1 = s[k_l + 1][n_l];
    float v8 = s[k_l + 8][n_l], v9 = s[k_l + 9][n_l];
    float h0 = bfr(v0), h1 = bfr(v1), h8 = bfr(v8), h9 = bfr(v9);
    size_t base = ((size_t)((n0 >> 3) + nb) * NKB16 + (k0 >> 4) + kb2) * 64 + lane * 2;
    *(uint2*)&g_Whi[base] = make_uint2(bf2(h0, h1), bf2(h8, h9));
    *(uint2*)&g_Wlo[base] = make_uint2(bf2(v0 - h0, v1 - h1), bf2(v8 - h8, v9 - h9));
}

// ---------------- xin = x @ x2h for all timesteps (one-time) -----------------
__global__ void xin_kernel(const float* __restrict__ x, const float* __restrict__ x2h) {
    __shared__ float sx[64][NI];
    const int tid = threadIdx.x;
    const int r0 = blockIdx.x * 64;
    const int n = blockIdx.y * 256 + tid;
    for (int s = tid; s < 64 * NI; s += 256) {
        int r = s >> 5, i = s & 31;
        int R = r0 + r;
        int tt = R >> 7, bb = R & 127;
        sx[r][i] = x[((size_t)bb * T_STEPS + tt) * NI + i];
    }
    __syncthreads();
    float acc[64];
#pragma unroll
    for (int r = 0; r < 64; r++) acc[r] = 0.0f;
#pragma unroll
    for (int i = 0; i < NI; i++) {
        float w = x2h[(size_t)i * NH + n];
#pragma unroll
        for (int r = 0; r < 64; r++) acc[r] = fmaf(sx[r][i], w, acc[r]);
    }
#pragma unroll
    for (int r = 0; r < 64; r++)
        g_xin[(size_t)(r0 + r) * NH + n] = acc[r];
}

// ---------------- persistent kernel: all 200 steps ---------------------------
// grid (16, 8) = 128 CTAs (all resident), 512 threads.
// CTA tile 128(M) x 128(N) x 256(K); warp grid 4x4, warp tile 32x32.
// W hi/lo resident in smem; A double-buffered per chunk (KC=64).
// Sync: one step-start gate on 2 producer ntiles; per-ntile GEMM barrier;
// parity-buffered partials. No global barrier.
__global__ void __launch_bounds__(NTHREADS, 1) step_kernel(
    const float* __restrict__ gamma, const float* __restrict__ eps,
    float* __restrict__ out)
{
    extern __shared__ uint32_t smu[];

    const int tid = threadIdx.x;
    const int warp = tid >> 5, lane = tid & 31;
    const int warpM = warp >> 2, warpN = warp & 3;
    const int ntile = blockIdx.x, kb = blockIdx.y;
    const int n0 = ntile * NT;
    const int kb16 = kb * (KSLICE / 16);     // first kblk16 of this CTA (kb*16)
    const int depA = 2 * kb, depB = 2 * kb + 1;   // producer ntiles of this CTA's A slice

    float* out_hy  = out;
    float* out_hz  = out + (size_t)T_STEPS * B * NH;
    float* out_hyu = out_hz + (size_t)T_STEPS * B * PORT;
    float* out_spk = out_hyu + (size_t)T_STEPS * B * PORT;

    // ---- one-time W residency load: 16 nblk x 16 kblk x 64 u32, hi+lo -------
    {
#pragma unroll
        for (int it = 0; it < 8; it++) {
            int i = tid + it * NTHREADS;           // 0..4095
            int piece = i >> 4, j = i & 15;        // 256 pieces x 16 cps
            int nblk = piece >> 4, kblk = piece & 15;
            size_t gsrc = ((size_t)((n0 >> 3) + nblk) * NKB16 + kb16 + kblk) * 64 + j * 4;
            cpa16(smem_u32(smu + WHI_OFF + piece * 64 + j * 4), g_Whi + gsrc);
            cpa16(smem_u32(smu + WLO_OFF + piece * 64 + j * 4), g_Wlo + gsrc);
        }
        CP_COMMIT(); CP_WAIT(0);
        __syncthreads();
    }

    const bool harm = (n0 < PORT);
    const int nl4 = lane * 4;
    const int n4 = n0 + nl4;
    float4 gm = make_float4(0, 0, 0, 0), epv = make_float4(0, 0, 0, 0);
    if (harm) { gm = *(const float4*)&gamma[n4]; epv = *(const float4*)&eps[n4]; }

    for (int t = 0; t < T_STEPS; t++) {
        const int src = t & 1, dst = src ^ 1;
        const uint32_t* __restrict__ Ahi = g_Ahi[src];
        const uint32_t* __restrict__ Alo = g_Alo[src];
        float* __restrict__ part = g_part[t & 1];

        // ---- step-start gate: producer ntiles' epilogues of step t-1 done ----
        if (t > 0) {
            if (tid == 0) {
                const int need = SPLITK * t;
                while (((volatile int*)g_epn)[depA] < need) {}
                while (((volatile int*)g_epn)[depB] < need) {}
            }
            __syncthreads();
            __threadfence();   // acquire for A[src] reads
        }

        // ---- cp.async stage of one A chunk (4 kblk16) into buf (c & 1) ----
        auto issueA = [&](int c) {
            uint32_t* bb = smu + (c & 1) * ABUF_U32;
            const int kc = kb16 + c * 4;
#pragma unroll
            for (int it = 0; it < 2; it++) {
                int i = tid + it * NTHREADS;
                int piece = i >> 5, j = i & 31;
                int mblk = piece >> 2, kk = piece & 3;
                size_t gsrc = ((size_t)mblk * NKB16 + kc + kk) * 128 + j * 4;
                cpa16(smem_u32(bb + piece * 128 + j * 4), Ahi + gsrc);
                cpa16(smem_u32(bb + 4096 + piece * 128 + j * 4), Alo + gsrc);
            }
        };

        float C[2][4][4];
#pragma unroll
        for (int mi = 0; mi < 2; mi++)
#pragma unroll
            for (int ni = 0; ni < 4; ni++)
#pragma unroll
                for (int q = 0; q < 4; q++) C[mi][ni][q] = 0.0f;

        issueA(0); CP_COMMIT();
        for (int c = 0; c < NCHUNK; c++) {
            if (c < NCHUNK - 1) { issueA(c + 1); CP_COMMIT(); CP_WAIT(1); }
            else                { CP_WAIT(0); }
            __syncthreads();
            const uint32_t* tAhi = smu + (c & 1) * ABUF_U32;
            const uint32_t* tAlo = tAhi + 4096;

#pragma unroll
            for (int ks = 0; ks < 4; ks++) {
                uint32_t a[2][4], bh[4][2], bl[4][2];
#pragma unroll
                for (int mi = 0; mi < 2; mi++) {
                    uint4 v = *(const uint4*)&tAhi[((warpM * 2 + mi) * 4 + ks) * 128 + lane * 4];
                    a[mi][0] = v.x; a[mi][1] = v.y; a[mi][2] = v.z; a[mi][3] = v.w;
                }
#pragma unroll
                for (int ni = 0; ni < 4; ni++) {
                    int woff = ((warpN * 4 + ni) * 16 + c * 4 + ks) * 64 + lane * 2;
                    uint2 h = *(const uint2*)&smu[WHI_OFF + woff];
                    uint2 l = *(const uint2*)&smu[WLO_OFF + woff];
                    bh[ni][0] = h.x; bh[ni][1] = h.y;
                    bl[ni][0] = l.x; bl[ni][1] = l.y;
                }
#pragma unroll
                for (int mi = 0; mi < 2; mi++)
#pragma unroll
                    for (int ni = 0; ni < 4; ni++) {
                        mma_bf16(C[mi][ni], a[mi], bh[ni]);   // Ahi * Whi
                        mma_bf16(C[mi][ni], a[mi], bl[ni]);   // Ahi * Wlo
                    }
#pragma unroll
                for (int mi = 0; mi < 2; mi++) {
                    uint4 v = *(const uint4*)&tAlo[((warpM * 2 + mi) * 4 + ks) * 128 + lane * 4];
                    a[mi][0] = v.x; a[mi][1] = v.y; a[mi][2] = v.z; a[mi][3] = v.w;
                }
#pragma unroll
                for (int mi = 0; mi < 2; mi++)
#pragma unroll
                    for (int ni = 0; ni < 4; ni++)
                        mma_bf16(C[mi][ni], a[mi], bh[ni]);   // Alo * Whi
            }
            __syncthreads();
        }

        // ---- write split-K partials (parity buffer) ----
        const int r = lane >> 2, cc = lane & 3;
#pragma unroll
        for (int mi = 0; mi < 2; mi++)
#pragma unroll
            for (int ni = 0; ni < 4; ni++) {
                int row = warpM * 32 + mi * 16 + r;
                int col = n0 + warpN * 32 + ni * 8 + cc * 2;
                float2 v0 = make_float2(C[mi][ni][0], C[mi][ni][1]);
                float2 v1 = make_float2(C[mi][ni][2], C[mi][ni][3]);
                *(float2*)&part[((size_t)kb * B + row) * NH + col]     = v0;
                *(float2*)&part[((size_t)kb * B + row + 8) * NH + col] = v1;
            }

        // ---- per-ntile barrier: all 8 split-K CTAs must arrive ---------------
        __threadfence();
        __syncthreads();
        if (tid == 0) {
            atomicAdd(&g_cnt[ntile], 1);
            while (((volatile int*)g_cnt)[ntile] < SPLITK * (t + 1)) {}
        }
        __syncthreads();
        __threadfence();   // acquire: order partial reads after arrivals

        // ---- distributed epilogue: this CTA handles rows [kb*16, kb*16+16) --
        {
            float (*sV)[132] = (float(*)[132])smu;   // staging [16][132]
            const float* old_hy = out_hy + (size_t)(t - 1) * B * NH;

            const int lb = warp;                 // local row 0..15 (one per warp)
            const int b = kb * 16 + lb;
            const size_t ob = (size_t)t * B + b;

            float4 pre = make_float4(0, 0, 0, 0);
#pragma unroll
            for (int q = 0; q < SPLITK; q++) {
                float4 pv = *(const float4*)&part[((size_t)q * B + b) * NH + n4];
                pre.x += pv.x; pre.y += pv.y; pre.z += pv.z; pre.w += pv.w;
            }
            float4 xv = *(const float4*)&g_xin[((size_t)t * B + b) * NH + n4];
            pre.x += xv.x; pre.y += xv.y; pre.z += xv.z; pre.w += xv.w;

            float4 f;
            f.x = tanhf(pre.x); f.y = tanhf(pre.y);
            f.z = tanhf(pre.z); f.w = tanhf(pre.w);

            float4 old = make_float4(0, 0, 0, 0);
            if (t > 0) old = *(const float4*)&old_hy[(size_t)b * NH + n4];

            float4 newv;
            if (harm) {
                float4 hzo = *(const float4*)&g_hz[(size_t)b * PORT + n4];
                float4 hzn;
                hzn.x = hzo.x + DT * (f.x - gm.x * old.x - epv.x * hzo.x);
                hzn.y = hzo.y + DT * (f.y - gm.y * old.y - epv.y * hzo.y);
                hzn.z = hzo.z + DT * (f.z - gm.z * old.z - epv.z * hzo.z);
                hzn.w = hzo.w + DT * (f.w - gm.w * old.w - epv.w * hzo.w);
                newv.x = old.x + DT * hzn.x;
                newv.y = old.y + DT * hzn.y;
                newv.z = old.z + DT * hzn.z;
                newv.w = old.w + DT * hzn.w;
                *(float4*)&out_hy[ob * NH + n4]   = newv;
                *(float4*)&out_hz[ob * PORT + n4] = hzn;
                *(float4*)&g_hz[(size_t)b * PORT + n4] = hzn;
            } else {
                int j4 = n4 - PORT;
                float4 spk, u;
                spk.x = (old.x > THRESH) ? 1.0f : 0.0f;
                spk.y = (old.y > THRESH) ? 1.0f : 0.0f;
                spk.z = (old.z > THRESH) ? 1.0f : 0.0f;
                spk.w = (old.w > THRESH) ? 1.0f : 0.0f;
                u.x = (spk.x > 0.0f) ? 0.0f : old.x;
                u.y = (spk.y > 0.0f) ? 0.0f : old.y;
                u.z = (spk.z > 0.0f) ? 0.0f : old.z;
                u.w = (spk.w > 0.0f) ? 0.0f : old.w;
                newv.x = u.x + DT * (f.x - u.x);
                newv.y = u.y + DT * (f.y - u.y);
                newv.z = u.z + DT * (f.z - u.z);
                newv.w = u.w + DT * (f.w - u.w);
                *(float4*)&out_hy[ob * NH + n4]    = newv;
                *(float4*)&out_hyu[ob * PORT + j4] = newv;
                *(float4*)&out_spk[ob * PORT + j4] = spk;
            }
            *(float4*)&sV[lb][nl4] = newv;
            __syncthreads();

            // ---- packed bf16 hi/lo A writeback: mblk = kb, warps 0..7 --------
            if (warp < 8) {
                uint32_t* hyhi_d = g_Ahi[dst];
                uint32_t* hylo_d = g_Alo[dst];
                const int fr = lane >> 2, fc = (lane & 3) * 2;
                const int kl = warp;             // local kblk16 0..7
                int r0 = fr, r1 = fr + 8;        // local sV rows
                int c0 = kl * 16 + fc;
                float v00 = sV[r0][c0], v01 = sV[r0][c0 + 1];
                float v10 = sV[r1][c0], v11 = sV[r1][c0 + 1];
                float v08 = sV[r0][c0 + 8], v09 = sV[r0][c0 + 9];
                float v18 = sV[r1][c0 + 8], v19 = sV[r1][c0 + 9];
                float h00 = bfr(v00), h01 = bfr(v01), h10 = bfr(v10), h11 = bfr(v11);
                float h08 = bfr(v08), h09 = bfr(v09), h18 = bfr(v18), h19 = bfr(v19);
                uint4 hi, lo;
                hi.x = bf2(h00, h01); lo.x = bf2(v00 - h00, v01 - h01);
                hi.y = bf2(h10, h11); lo.y = bf2(v10 - h10, v11 - h11);
                hi.z = bf2(h08, h09); lo.z = bf2(v08 - h08, v09 - h09);
                hi.w = bf2(h18, h19); lo.w = bf2(v18 - h18, v19 - h19);
                size_t goff = ((size_t)kb * NKB16 + (n0 >> 4) + kl) * 128 + lane * 4;
                *(uint4*)&hyhi_d[goff] = hi;
                *(uint4*)&hylo_d[goff] = lo;
            }
            __threadfence();
            __syncthreads();
            if (tid == 0) atomicAdd(&g_epn[ntile], 1);   // release this ntile's A slice
        }
        // no global barrier — next step's gate enforces the dataflow
    }
}

// ---------------- launch ------------------------------------------------------
extern "C" void kernel_launch(void* const* d_in, const int* in_sizes, int n_in,
                              void* d_out, int out_size) {
    (void)in_sizes; (void)n_in; (void)out_size;
    const float* x     = (const float*)d_in[0];
    const float* x2h   = (const float*)d_in[1];
    const float* h2h   = (const float*)d_in[2];
    const float* gamma = (const float*)d_in[3];
    const float* eps   = (const float*)d_in[4];
    float* out = (float*)d_out;

    cudaFuncSetAttribute(step_kernel, cudaFuncAttributeMaxDynamicSharedMemorySize, SMEM_BYTES);

    init_kernel<<<256, 1024>>>();
    prep_kernel<<<dim3(NH / 64, NH / 32), 512>>>(h2h);
    xin_kernel<<<dim3((T_STEPS * B) / 64, NH / 256), 256>>>(x, x2h);
    step_kernel<<<dim3(NTILES, SPLITK), NTHREADS, SMEM_BYTES>>>(gamma, eps, out);
}